// round 4
// baseline (speedup 1.0000x reference)
#include <cuda_runtime.h>
#include <math.h>

#define B       16
#define N       128
#define NC      80
#define HW0     25600
#define HW1     6400
#define HW2     1600
#define CHUNK   1600
#define NTUP    (3 * B * N)          // 6144 tuples
#define CH0     (HW0 / CHUNK)        // 16
#define CH1     (HW1 / CHUNK)        // 4
#define CH2     (HW2 / CHUNK)        // 1
#define NCHUNKS (CH0 + CH1 + CH2)    // 21

// Scratch (no device allocations allowed)
__device__ unsigned long long g_keys[NTUP];
__device__ float g_tup[3 * NTUP];

// ---------------------------------------------------------------------------
// Kernel 1: init packed argmin keys
// ---------------------------------------------------------------------------
__global__ void init_keys_kernel() {
    int i = blockIdx.x * blockDim.x + threadIdx.x;
    if (i < NTUP) g_keys[i] = 0xFFFFFFFFFFFFFFFFULL;
}

// ---------------------------------------------------------------------------
// Kernel 2: nearest-pred search.
// Block: 256 threads = 32 lanes (preds) x 8 rows (gt groups of 16).
// d2 = (gx-px)^2 + (gy-py)^2 computed directly (reference rounding scale).
// Cross-block combine via atomicMin on packed (d2_bits, idx) u64 key
// (d2 >= 0, so float order == uint order; low idx wins ties like argmin).
// ---------------------------------------------------------------------------
__global__ __launch_bounds__(256, 2)
void argmin_kernel(const float* __restrict__ reg0,
                   const float* __restrict__ reg1,
                   const float* __restrict__ reg2,
                   const float* __restrict__ gt) {
    const int b  = blockIdx.y;
    const int bx = blockIdx.x;

    int lvl, chunk, HW;
    const float* reg;
    if (bx < CH0)            { lvl = 0; chunk = bx;               HW = HW0; reg = reg0; }
    else if (bx < CH0 + CH1) { lvl = 1; chunk = bx - CH0;         HW = HW1; reg = reg1; }
    else                     { lvl = 2; chunk = bx - (CH0 + CH1); HW = HW2; reg = reg2; }

    const int tx = threadIdx.x & 31;
    const int ty = threadIdx.x >> 5;   // 0..7, handles gts [ty*16, ty*16+16)

    float gx[16], gy[16], tmin[16];
    int   imin[16];
    const float* gtb = gt + ((size_t)b * N + ty * 16) * 4;
#pragma unroll
    for (int i = 0; i < 16; i++) {
        gx[i]   = gtb[i * 4 + 0];
        gy[i]   = gtb[i * 4 + 1];
        tmin[i] = __int_as_float(0x7F800000);  // +inf
        imin[i] = 0;
    }

    const float* regb = reg + (size_t)b * HW * 4;
    const int pend = chunk * CHUNK + CHUNK;

    for (int p = chunk * CHUNK + tx; p < pend; p += 32) {
        float4 v = *reinterpret_cast<const float4*>(regb + (size_t)p * 4);
        float px = v.x, py = v.y;
#pragma unroll
        for (int i = 0; i < 16; i++) {
            float dx = gx[i] - px;
            float dy = gy[i] - py;
            float d2 = dx * dx + dy * dy;
            if (d2 < tmin[i]) { tmin[i] = d2; imin[i] = p; }  // strict <: first occurrence in lane
        }
    }

    // Warp reduce (d2, idx) lexicographic; lane 0 does global atomicMin.
#pragma unroll
    for (int i = 0; i < 16; i++) {
        float t  = tmin[i];
        int   id = imin[i];
#pragma unroll
        for (int off = 16; off > 0; off >>= 1) {
            float t2  = __shfl_xor_sync(0xFFFFFFFFu, t, off);
            int   id2 = __shfl_xor_sync(0xFFFFFFFFu, id, off);
            if (t2 < t || (t2 == t && id2 < id)) { t = t2; id = id2; }
        }
        if (tx == 0) {
            unsigned long long key =
                ((unsigned long long)__float_as_uint(t) << 32) | (unsigned)id;
            atomicMin(&g_keys[((size_t)lvl * B + b) * N + ty * 16 + i], key);
        }
    }
}

// ---------------------------------------------------------------------------
// Kernel 3: one warp per (lvl, b, gt) tuple: gather + CE + L1.
// ---------------------------------------------------------------------------
__global__ __launch_bounds__(256)
void gather_kernel(const float* __restrict__ cls0,
                   const float* __restrict__ cls1,
                   const float* __restrict__ cls2,
                   const float* __restrict__ reg0,
                   const float* __restrict__ reg1,
                   const float* __restrict__ reg2,
                   const float* __restrict__ gt,
                   const int*   __restrict__ labels) {
    const int w    = (blockIdx.x * blockDim.x + threadIdx.x) >> 5;
    const int lane = threadIdx.x & 31;
    if (w >= NTUP) return;

    const int lvl = w / (B * N);
    const int rem = w - lvl * (B * N);
    const int b   = rem / N;
    const int g   = rem - b * N;

    const float* cls; const float* reg; int HW;
    if (lvl == 0)      { cls = cls0; reg = reg0; HW = HW0; }
    else if (lvl == 1) { cls = cls1; reg = reg1; HW = HW1; }
    else               { cls = cls2; reg = reg2; HW = HW2; }

    unsigned long long key = g_keys[w];
    unsigned id = (unsigned)key;
    float d2 = __uint_as_float((unsigned)(key >> 32));
    float wgt = (sqrtf(d2) < 2.5f) ? 1.0f : 0.0f;  // match reference boundary rounding

    const float* gtr = gt + ((size_t)b * N + g) * 4;

    // CE via warp logsumexp over 80 classes
    const float* crow = cls + ((size_t)b * HW + id) * NC;
    float x0 = -__int_as_float(0x7F800000), x1 = x0, x2 = x0;
    if (lane < NC)      x0 = crow[lane];
    if (lane + 32 < NC) x1 = crow[lane + 32];
    if (lane + 64 < NC) x2 = crow[lane + 64];
    float mx = fmaxf(x0, fmaxf(x1, x2));
#pragma unroll
    for (int off = 16; off > 0; off >>= 1)
        mx = fmaxf(mx, __shfl_xor_sync(0xFFFFFFFFu, mx, off));
    float sm = 0.0f;
    if (lane < NC)      sm += expf(x0 - mx);
    if (lane + 32 < NC) sm += expf(x1 - mx);
    if (lane + 64 < NC) sm += expf(x2 - mx);
#pragma unroll
    for (int off = 16; off > 0; off >>= 1)
        sm += __shfl_xor_sync(0xFFFFFFFFu, sm, off);
    float lse = mx + logf(sm);

    if (lane == 0) {
        int lab = labels[b * N + g];
        float ce = lse - crow[lab];

        const float* rrow = reg + ((size_t)b * HW + id) * 4;
        float l1 = fabsf(rrow[0] - gtr[0]) + fabsf(rrow[1] - gtr[1]) +
                   fabsf(rrow[2] - gtr[2]) + fabsf(rrow[3] - gtr[3]);

        g_tup[w]             = ce * wgt;
        g_tup[NTUP + w]      = l1 * wgt;
        g_tup[2 * NTUP + w]  = wgt;
    }
}

// ---------------------------------------------------------------------------
// Kernel 4: deterministic final reduction -> 3 outputs.
// ---------------------------------------------------------------------------
__global__ __launch_bounds__(256)
void finalize_kernel(float* __restrict__ out) {
    __shared__ float s0[256], s1[256], s2[256];
    int tid = threadIdx.x;
    float a = 0.0f, c = 0.0f, nn = 0.0f;
    for (int i = tid; i < NTUP; i += 256) {
        a  += g_tup[i];
        c  += g_tup[NTUP + i];
        nn += g_tup[2 * NTUP + i];
    }
    s0[tid] = a; s1[tid] = c; s2[tid] = nn;
    __syncthreads();
    for (int off = 128; off > 0; off >>= 1) {
        if (tid < off) {
            s0[tid] += s0[tid + off];
            s1[tid] += s1[tid + off];
            s2[tid] += s2[tid + off];
        }
        __syncthreads();
    }
    if (tid == 0) {
        float np    = s2[0];
        float denom = fmaxf(np, 1.0f);
        out[0] = s0[0] / denom;
        out[1] = s1[0] / denom;
        out[2] = np;
    }
}

// ---------------------------------------------------------------------------
// Bind inputs BY ELEMENT COUNT (metadata order is interleaved:
// cls_0, reg_0, cls_1, reg_1, cls_2, reg_2, gt, labels — this was the R1/R2
// bug). All 8 counts are distinct, so size-based binding is unambiguous.
// ---------------------------------------------------------------------------
extern "C" void kernel_launch(void* const* d_in, const int* in_sizes, int n_in,
                              void* d_out, int out_size) {
    const float* cls0 = 0; const float* cls1 = 0; const float* cls2 = 0;
    const float* reg0 = 0; const float* reg1 = 0; const float* reg2 = 0;
    const float* gt   = 0; const int*   lab  = 0;

    for (int i = 0; i < n_in; i++) {
        switch (in_sizes[i]) {
            case B * HW0 * NC: cls0 = (const float*)d_in[i]; break;  // 32,768,000
            case B * HW1 * NC: cls1 = (const float*)d_in[i]; break;  //  8,192,000
            case B * HW2 * NC: cls2 = (const float*)d_in[i]; break;  //  2,048,000
            case B * HW0 * 4:  reg0 = (const float*)d_in[i]; break;  //  1,638,400
            case B * HW1 * 4:  reg1 = (const float*)d_in[i]; break;  //    409,600
            case B * HW2 * 4:  reg2 = (const float*)d_in[i]; break;  //    102,400
            case B * N * 4:    gt   = (const float*)d_in[i]; break;  //      8,192
            case B * N:        lab  = (const int*)d_in[i];   break;  //      2,048
        }
    }
    float* out = (float*)d_out;

    init_keys_kernel<<<(NTUP + 255) / 256, 256>>>();

    dim3 grid(NCHUNKS, B);
    argmin_kernel<<<grid, 256>>>(reg0, reg1, reg2, gt);

    int nwarp_blocks = (NTUP * 32 + 255) / 256;  // 768 blocks, 8 warps each
    gather_kernel<<<nwarp_blocks, 256>>>(cls0, cls1, cls2, reg0, reg1, reg2, gt, lab);

    finalize_kernel<<<1, 256>>>(out);
}

// round 6
// speedup vs baseline: 1.3454x; 1.3454x over previous
#include <cuda_runtime.h>
#include <math.h>

#define B       16
#define N       128
#define NC      80
#define HW0     25600
#define HW1     6400
#define HW2     1600
#define CHUNK   1600
#define NTUP    (3 * B * N)          // 6144 tuples
#define CH0     (HW0 / CHUNK)        // 16
#define CH1     (HW1 / CHUNK)        // 4
#define CH2     (HW2 / CHUNK)        // 1
#define NCHUNKS (CH0 + CH1 + CH2)    // 21
#define GBLOCKS (NTUP / 8)           // 768 gather blocks (8 warps each)

// Scratch (no device allocations allowed)
__device__ unsigned long long g_part[NCHUNKS][B][N];  // per-chunk argmin partials
__device__ float        g_blk[3][GBLOCKS];            // per-block loss partials
__device__ unsigned int g_count;                      // last-block ticket (zero-init; reset each run)

// ---------------------------------------------------------------------------
// Kernel 1: per-chunk nearest-pred search, NO atomics, NO init needed.
// Grid (NCHUNKS, B, 2). Block 256 = 32 lanes x 8 rows; each thread holds 8 gts
// (z selects gt half). d2 = (gx-px)^2+(gy-py)^2 computed directly (reference
// rounding scale -- required for argmin agreement).
// Writes packed (d2_bits<<32 | idx) partial key per (chunk, b, gt).
// ---------------------------------------------------------------------------
__global__ __launch_bounds__(256)
void argmin_kernel(const float* __restrict__ reg0,
                   const float* __restrict__ reg1,
                   const float* __restrict__ reg2,
                   const float* __restrict__ gt) {
    const int bx = blockIdx.x;   // chunk slot 0..20
    const int b  = blockIdx.y;
    const int gh = blockIdx.z;   // gt half

    int chunk, HW;
    const float* reg;
    if (bx < CH0)            { chunk = bx;               HW = HW0; reg = reg0; }
    else if (bx < CH0 + CH1) { chunk = bx - CH0;         HW = HW1; reg = reg1; }
    else                     { chunk = bx - (CH0 + CH1); HW = HW2; reg = reg2; }

    const int tx = threadIdx.x & 31;
    const int ty = threadIdx.x >> 5;           // 0..7
    const int gbase = gh * 64 + ty * 8;        // first of this thread's 8 gts

    float gx[8], gy[8], tmin[8];
    int   imin[8];
    const float* gtb = gt + ((size_t)b * N + gbase) * 4;
#pragma unroll
    for (int i = 0; i < 8; i++) {
        gx[i]   = gtb[i * 4 + 0];
        gy[i]   = gtb[i * 4 + 1];
        tmin[i] = __int_as_float(0x7F800000);  // +inf
        imin[i] = 0;
    }

    const float* regb = reg + (size_t)b * HW * 4;
    const int pend = chunk * CHUNK + CHUNK;

#pragma unroll 2
    for (int p = chunk * CHUNK + tx; p < pend; p += 32) {
        float4 v = *reinterpret_cast<const float4*>(regb + (size_t)p * 4);
        float px = v.x, py = v.y;
#pragma unroll
        for (int i = 0; i < 8; i++) {
            float dx = gx[i] - px;
            float dy = gy[i] - py;
            float d2 = dx * dx + dy * dy;
            if (d2 < tmin[i]) { tmin[i] = d2; imin[i] = p; }  // strict <: first occurrence
        }
    }

    // Warp reduce (d2, idx) lexicographic; lane 0 writes partial (no atomic).
#pragma unroll
    for (int i = 0; i < 8; i++) {
        float t  = tmin[i];
        int   id = imin[i];
#pragma unroll
        for (int off = 16; off > 0; off >>= 1) {
            float t2  = __shfl_xor_sync(0xFFFFFFFFu, t, off);
            int   id2 = __shfl_xor_sync(0xFFFFFFFFu, id, off);
            if (t2 < t || (t2 == t && id2 < id)) { t = t2; id = id2; }
        }
        if (tx == 0) {
            g_part[bx][b][gbase + i] =
                ((unsigned long long)__float_as_uint(t) << 32) | (unsigned)id;
        }
    }
}

// ---------------------------------------------------------------------------
// Kernel 2: fused gather + CE/L1 + full deterministic reduction.
// One warp per (lvl, b, gt) tuple; 8 warps/block, GBLOCKS blocks.
// Last block (ticket pattern) reduces all block partials and writes outputs.
// ---------------------------------------------------------------------------
__global__ __launch_bounds__(256)
void gather_kernel(const float* __restrict__ cls0,
                   const float* __restrict__ cls1,
                   const float* __restrict__ cls2,
                   const float* __restrict__ reg0,
                   const float* __restrict__ reg1,
                   const float* __restrict__ reg2,
                   const float* __restrict__ gt,
                   const int*   __restrict__ labels,
                   float*       __restrict__ out) {
    const int wib  = threadIdx.x >> 5;                  // warp in block 0..7
    const int w    = blockIdx.x * 8 + wib;              // tuple id
    const int lane = threadIdx.x & 31;

    const int lvl = w / (B * N);
    const int rem = w - lvl * (B * N);
    const int b   = rem / N;
    const int g   = rem - b * N;

    const float* cls; const float* reg; int HW, s0, nch;
    if (lvl == 0)      { cls = cls0; reg = reg0; HW = HW0; s0 = 0;         nch = CH0; }
    else if (lvl == 1) { cls = cls1; reg = reg1; HW = HW1; s0 = CH0;       nch = CH1; }
    else               { cls = cls2; reg = reg2; HW = HW2; s0 = CH0 + CH1; nch = CH2; }

    // Min over this level's chunk partials (lane c holds chunk c's key).
    unsigned long long key = 0xFFFFFFFFFFFFFFFFULL;
    if (lane < nch) key = g_part[s0 + lane][b][g];
#pragma unroll
    for (int off = 16; off > 0; off >>= 1) {
        unsigned long long k2 = __shfl_xor_sync(0xFFFFFFFFu, key, off);
        key = (k2 < key) ? k2 : key;
    }
    // key now uniform across warp
    unsigned id = (unsigned)key;
    float d2  = __uint_as_float((unsigned)(key >> 32));
    float wgt = (sqrtf(d2) < 2.5f) ? 1.0f : 0.0f;

    const float* gtr = gt + ((size_t)b * N + g) * 4;

    // CE via warp logsumexp over 80 classes
    const float* crow = cls + ((size_t)b * HW + id) * NC;
    float x0 = -__int_as_float(0x7F800000), x1 = x0, x2 = x0;
    if (lane < NC)      x0 = crow[lane];
    if (lane + 32 < NC) x1 = crow[lane + 32];
    if (lane + 64 < NC) x2 = crow[lane + 64];
    float mx = fmaxf(x0, fmaxf(x1, x2));
#pragma unroll
    for (int off = 16; off > 0; off >>= 1)
        mx = fmaxf(mx, __shfl_xor_sync(0xFFFFFFFFu, mx, off));
    float sm = 0.0f;
    if (lane < NC)      sm += expf(x0 - mx);
    if (lane + 32 < NC) sm += expf(x1 - mx);
    if (lane + 64 < NC) sm += expf(x2 - mx);
#pragma unroll
    for (int off = 16; off > 0; off >>= 1)
        sm += __shfl_xor_sync(0xFFFFFFFFu, sm, off);
    float lse = mx + logf(sm);

    __shared__ float s_ce[8], s_l1[8], s_w[8];
    __shared__ int   s_last;

    if (lane == 0) {
        int lab = labels[b * N + g];
        float ce = lse - crow[lab];
        const float* rrow = reg + ((size_t)b * HW + id) * 4;
        float l1 = fabsf(rrow[0] - gtr[0]) + fabsf(rrow[1] - gtr[1]) +
                   fabsf(rrow[2] - gtr[2]) + fabsf(rrow[3] - gtr[3]);
        s_ce[wib] = ce * wgt;
        s_l1[wib] = l1 * wgt;
        s_w[wib]  = wgt;
    }
    __syncthreads();

    // Block partials + ticket
    if (threadIdx.x == 0) {
        float a = 0.0f, c = 0.0f, nn = 0.0f;
#pragma unroll
        for (int i = 0; i < 8; i++) { a += s_ce[i]; c += s_l1[i]; nn += s_w[i]; }
        g_blk[0][blockIdx.x] = a;
        g_blk[1][blockIdx.x] = c;
        g_blk[2][blockIdx.x] = nn;
        __threadfence();
        unsigned t = atomicAdd(&g_count, 1u);
        s_last = (t == GBLOCKS - 1);
    }
    __syncthreads();

    if (!s_last) return;

    // Last block: deterministic tree reduction of GBLOCKS partials.
    __shared__ float r0[256], r1[256], r2[256];
    int tid = threadIdx.x;
    float a = 0.0f, c = 0.0f, nn = 0.0f;
    for (int i = tid; i < GBLOCKS; i += 256) {
        a  += g_blk[0][i];
        c  += g_blk[1][i];
        nn += g_blk[2][i];
    }
    r0[tid] = a; r1[tid] = c; r2[tid] = nn;
    __syncthreads();
    for (int off = 128; off > 0; off >>= 1) {
        if (tid < off) {
            r0[tid] += r0[tid + off];
            r1[tid] += r1[tid + off];
            r2[tid] += r2[tid + off];
        }
        __syncthreads();
    }
    if (tid == 0) {
        float np    = r2[0];
        float denom = fmaxf(np, 1.0f);
        out[0] = r0[0] / denom;
        out[1] = r1[0] / denom;
        out[2] = np;
        g_count = 0;   // reset ticket for next graph replay
    }
}

// ---------------------------------------------------------------------------
// Bind inputs BY ELEMENT COUNT (metadata order is interleaved:
// cls_0, reg_0, cls_1, reg_1, cls_2, reg_2, gt, labels). All 8 element
// counts are distinct, so size-based binding is unambiguous.
// ---------------------------------------------------------------------------
extern "C" void kernel_launch(void* const* d_in, const int* in_sizes, int n_in,
                              void* d_out, int out_size) {
    const float* cls0 = 0; const float* cls1 = 0; const float* cls2 = 0;
    const float* reg0 = 0; const float* reg1 = 0; const float* reg2 = 0;
    const float* gt   = 0; const int*   lab  = 0;

    for (int i = 0; i < n_in; i++) {
        switch (in_sizes[i]) {
            case B * HW0 * NC: cls0 = (const float*)d_in[i]; break;  // 32,768,000
            case B * HW1 * NC: cls1 = (const float*)d_in[i]; break;  //  8,192,000
            case B * HW2 * NC: cls2 = (const float*)d_in[i]; break;  //  2,048,000
            case B * HW0 * 4:  reg0 = (const float*)d_in[i]; break;  //  1,638,400
            case B * HW1 * 4:  reg1 = (const float*)d_in[i]; break;  //    409,600
            case B * HW2 * 4:  reg2 = (const float*)d_in[i]; break;  //    102,400
            case B * N * 4:    gt   = (const float*)d_in[i]; break;  //      8,192
            case B * N:        lab  = (const int*)d_in[i];   break;  //      2,048
        }
    }

    dim3 grid(NCHUNKS, B, 2);
    argmin_kernel<<<grid, 256>>>(reg0, reg1, reg2, gt);

    gather_kernel<<<GBLOCKS, 256>>>(cls0, cls1, cls2, reg0, reg1, reg2, gt, lab,
                                    (float*)d_out);
}

// round 7
// speedup vs baseline: 1.5449x; 1.1483x over previous
#include <cuda_runtime.h>
#include <math.h>

#define B       16
#define N       128
#define NC      80
#define HW0     25600
#define HW1     6400
#define HW2     1600
#define CHUNK   800
#define NTUP    (3 * B * N)          // 6144 tuples
#define CH0     (HW0 / CHUNK)        // 32
#define CH1     (HW1 / CHUNK)        // 8
#define CH2     (HW2 / CHUNK)        // 2
#define NCHUNKS (CH0 + CH1 + CH2)    // 42
#define GBLOCKS (NTUP / 8)           // 768 gather blocks (8 warps each)

// Scratch (no device allocations allowed)
__device__ unsigned long long g_part[NCHUNKS][B][N];  // per-chunk argmin partials
__device__ float        g_blk[3][GBLOCKS];            // per-block loss partials
__device__ unsigned int g_count;                      // last-block ticket (zero-init; reset each run)

// Packed f32x2 ops (sm_103a; ptxas won't auto-fuse -- must be PTX)
#define PACK_F32X2(out, lo, hi) \
    asm("mov.b64 %0, {%1, %2};" : "=l"(out) : "f"(lo), "f"(hi))
#define UNPACK_F32X2(lo, hi, in) \
    asm("mov.b64 {%0, %1}, %2;" : "=f"(lo), "=f"(hi) : "l"(in))
#define ADD_F32X2(out, a, b) \
    asm("add.rn.f32x2 %0, %1, %2;" : "=l"(out) : "l"(a), "l"(b))
#define MUL_F32X2(out, a, b) \
    asm("mul.rn.f32x2 %0, %1, %2;" : "=l"(out) : "l"(a), "l"(b))
#define FMA_F32X2(out, a, b, c) \
    asm("fma.rn.f32x2 %0, %1, %2, %3;" : "=l"(out) : "l"(a), "l"(b), "l"(c))

// ---------------------------------------------------------------------------
// Kernel 1: per-chunk nearest-pred search, no atomics, no init needed.
// Grid (NCHUNKS, B, 2). Block 256 = 32 lanes x 8 rows; each thread holds 8 gts
// (z selects gt half), processed as 4 packed f32x2 pairs.
// d2 = (px-gx)^2 + (py-gy)^2 via mul+fma per lane -- same rounding as the
// scalar FMUL+FFMA version that measured rel_err ~1e-7.
// Writes packed (d2_bits<<32 | idx) partial key per (chunk, b, gt).
// ---------------------------------------------------------------------------
__global__ __launch_bounds__(256)
void argmin_kernel(const float* __restrict__ reg0,
                   const float* __restrict__ reg1,
                   const float* __restrict__ reg2,
                   const float* __restrict__ gt) {
    const int bx = blockIdx.x;   // chunk slot 0..41
    const int b  = blockIdx.y;
    const int gh = blockIdx.z;   // gt half

    int chunk, HW;
    const float* reg;
    if (bx < CH0)            { chunk = bx;               HW = HW0; reg = reg0; }
    else if (bx < CH0 + CH1) { chunk = bx - CH0;         HW = HW1; reg = reg1; }
    else                     { chunk = bx - (CH0 + CH1); HW = HW2; reg = reg2; }

    const int tx = threadIdx.x & 31;
    const int ty = threadIdx.x >> 5;           // 0..7
    const int gbase = gh * 64 + ty * 8;        // first of this thread's 8 gts

    // Pre-negated, packed gt coords: gnx[j] = (-gx[2j], -gx[2j+1])
    unsigned long long gnx[4], gny[4];
    float tmin[8];
    int   imin[8];
    const float* gtb = gt + ((size_t)b * N + gbase) * 4;
#pragma unroll
    for (int j = 0; j < 4; j++) {
        float a0 = -gtb[(2 * j    ) * 4 + 0];
        float a1 = -gtb[(2 * j + 1) * 4 + 0];
        float b0 = -gtb[(2 * j    ) * 4 + 1];
        float b1 = -gtb[(2 * j + 1) * 4 + 1];
        PACK_F32X2(gnx[j], a0, a1);
        PACK_F32X2(gny[j], b0, b1);
    }
#pragma unroll
    for (int i = 0; i < 8; i++) {
        tmin[i] = __int_as_float(0x7F800000);  // +inf
        imin[i] = 0;
    }

    const float* regb = reg + (size_t)b * HW * 4;
    const int pend = chunk * CHUNK + CHUNK;

#pragma unroll 5
    for (int p = chunk * CHUNK + tx; p < pend; p += 32) {
        float4 v = *reinterpret_cast<const float4*>(regb + (size_t)p * 4);
        unsigned long long pxx, pyy;
        PACK_F32X2(pxx, v.x, v.x);
        PACK_F32X2(pyy, v.y, v.y);
#pragma unroll
        for (int j = 0; j < 4; j++) {
            unsigned long long dx2, dy2, m, d2v;
            ADD_F32X2(dx2, gnx[j], pxx);     // (px-gx, px-gx')
            ADD_F32X2(dy2, gny[j], pyy);
            MUL_F32X2(m, dx2, dx2);
            FMA_F32X2(d2v, dy2, dy2, m);
            float d0, d1;
            UNPACK_F32X2(d0, d1, d2v);
            if (d0 < tmin[2 * j])     { tmin[2 * j]     = d0; imin[2 * j]     = p; }
            if (d1 < tmin[2 * j + 1]) { tmin[2 * j + 1] = d1; imin[2 * j + 1] = p; }
        }
    }

    // Warp reduce (d2, idx) lexicographic; lane 0 writes partial (no atomic).
#pragma unroll
    for (int i = 0; i < 8; i++) {
        float t  = tmin[i];
        int   id = imin[i];
#pragma unroll
        for (int off = 16; off > 0; off >>= 1) {
            float t2  = __shfl_xor_sync(0xFFFFFFFFu, t, off);
            int   id2 = __shfl_xor_sync(0xFFFFFFFFu, id, off);
            if (t2 < t || (t2 == t && id2 < id)) { t = t2; id = id2; }
        }
        if (tx == 0) {
            g_part[bx][b][gbase + i] =
                ((unsigned long long)__float_as_uint(t) << 32) | (unsigned)id;
        }
    }
}

// ---------------------------------------------------------------------------
// Kernel 2: fused gather + CE/L1 + full deterministic reduction.
// One warp per (lvl, b, gt) tuple; 8 warps/block, GBLOCKS blocks.
// Last block (ticket pattern) reduces all block partials and writes outputs.
// ---------------------------------------------------------------------------
__global__ __launch_bounds__(256)
void gather_kernel(const float* __restrict__ cls0,
                   const float* __restrict__ cls1,
                   const float* __restrict__ cls2,
                   const float* __restrict__ reg0,
                   const float* __restrict__ reg1,
                   const float* __restrict__ reg2,
                   const float* __restrict__ gt,
                   const int*   __restrict__ labels,
                   float*       __restrict__ out) {
    const int wib  = threadIdx.x >> 5;                  // warp in block 0..7
    const int w    = blockIdx.x * 8 + wib;              // tuple id
    const int lane = threadIdx.x & 31;

    const int lvl = w / (B * N);
    const int rem = w - lvl * (B * N);
    const int b   = rem / N;
    const int g   = rem - b * N;

    const float* cls; const float* reg; int HW, s0, nch;
    if (lvl == 0)      { cls = cls0; reg = reg0; HW = HW0; s0 = 0;         nch = CH0; }
    else if (lvl == 1) { cls = cls1; reg = reg1; HW = HW1; s0 = CH0;       nch = CH1; }
    else               { cls = cls2; reg = reg2; HW = HW2; s0 = CH0 + CH1; nch = CH2; }

    // Min over this level's chunk partials (lane c holds chunk c's key).
    unsigned long long key = 0xFFFFFFFFFFFFFFFFULL;
    if (lane < nch) key = g_part[s0 + lane][b][g];
#pragma unroll
    for (int off = 16; off > 0; off >>= 1) {
        unsigned long long k2 = __shfl_xor_sync(0xFFFFFFFFu, key, off);
        key = (k2 < key) ? k2 : key;
    }
    // key now uniform across warp
    unsigned id = (unsigned)key;
    float d2  = __uint_as_float((unsigned)(key >> 32));
    float wgt = (sqrtf(d2) < 2.5f) ? 1.0f : 0.0f;

    const float* gtr = gt + ((size_t)b * N + g) * 4;

    // CE via warp logsumexp over 80 classes
    const float* crow = cls + ((size_t)b * HW + id) * NC;
    float x0 = -__int_as_float(0x7F800000), x1 = x0, x2 = x0;
    if (lane < NC)      x0 = crow[lane];
    if (lane + 32 < NC) x1 = crow[lane + 32];
    if (lane + 64 < NC) x2 = crow[lane + 64];
    float mx = fmaxf(x0, fmaxf(x1, x2));
#pragma unroll
    for (int off = 16; off > 0; off >>= 1)
        mx = fmaxf(mx, __shfl_xor_sync(0xFFFFFFFFu, mx, off));
    float sm = 0.0f;
    if (lane < NC)      sm += expf(x0 - mx);
    if (lane + 32 < NC) sm += expf(x1 - mx);
    if (lane + 64 < NC) sm += expf(x2 - mx);
#pragma unroll
    for (int off = 16; off > 0; off >>= 1)
        sm += __shfl_xor_sync(0xFFFFFFFFu, sm, off);
    float lse = mx + logf(sm);

    __shared__ float s_ce[8], s_l1[8], s_w[8];
    __shared__ int   s_last;

    if (lane == 0) {
        int lab = labels[b * N + g];
        float ce = lse - crow[lab];
        const float* rrow = reg + ((size_t)b * HW + id) * 4;
        float l1 = fabsf(rrow[0] - gtr[0]) + fabsf(rrow[1] - gtr[1]) +
                   fabsf(rrow[2] - gtr[2]) + fabsf(rrow[3] - gtr[3]);
        s_ce[wib] = ce * wgt;
        s_l1[wib] = l1 * wgt;
        s_w[wib]  = wgt;
    }
    __syncthreads();

    // Block partials + ticket
    if (threadIdx.x == 0) {
        float a = 0.0f, c = 0.0f, nn = 0.0f;
#pragma unroll
        for (int i = 0; i < 8; i++) { a += s_ce[i]; c += s_l1[i]; nn += s_w[i]; }
        g_blk[0][blockIdx.x] = a;
        g_blk[1][blockIdx.x] = c;
        g_blk[2][blockIdx.x] = nn;
        __threadfence();
        unsigned t = atomicAdd(&g_count, 1u);
        s_last = (t == GBLOCKS - 1);
    }
    __syncthreads();

    if (!s_last) return;

    // Last block: deterministic tree reduction of GBLOCKS partials.
    __shared__ float r0[256], r1[256], r2[256];
    int tid = threadIdx.x;
    float a = 0.0f, c = 0.0f, nn = 0.0f;
    for (int i = tid; i < GBLOCKS; i += 256) {
        a  += g_blk[0][i];
        c  += g_blk[1][i];
        nn += g_blk[2][i];
    }
    r0[tid] = a; r1[tid] = c; r2[tid] = nn;
    __syncthreads();
    for (int off = 128; off > 0; off >>= 1) {
        if (tid < off) {
            r0[tid] += r0[tid + off];
            r1[tid] += r1[tid + off];
            r2[tid] += r2[tid + off];
        }
        __syncthreads();
    }
    if (tid == 0) {
        float np    = r2[0];
        float denom = fmaxf(np, 1.0f);
        out[0] = r0[0] / denom;
        out[1] = r1[0] / denom;
        out[2] = np;
        g_count = 0;   // reset ticket for next graph replay
    }
}

// ---------------------------------------------------------------------------
// Bind inputs BY ELEMENT COUNT (metadata order is interleaved:
// cls_0, reg_0, cls_1, reg_1, cls_2, reg_2, gt, labels). All 8 element
// counts are distinct, so size-based binding is unambiguous.
// ---------------------------------------------------------------------------
extern "C" void kernel_launch(void* const* d_in, const int* in_sizes, int n_in,
                              void* d_out, int out_size) {
    const float* cls0 = 0; const float* cls1 = 0; const float* cls2 = 0;
    const float* reg0 = 0; const float* reg1 = 0; const float* reg2 = 0;
    const float* gt   = 0; const int*   lab  = 0;

    for (int i = 0; i < n_in; i++) {
        switch (in_sizes[i]) {
            case B * HW0 * NC: cls0 = (const float*)d_in[i]; break;  // 32,768,000
            case B * HW1 * NC: cls1 = (const float*)d_in[i]; break;  //  8,192,000
            case B * HW2 * NC: cls2 = (const float*)d_in[i]; break;  //  2,048,000
            case B * HW0 * 4:  reg0 = (const float*)d_in[i]; break;  //  1,638,400
            case B * HW1 * 4:  reg1 = (const float*)d_in[i]; break;  //    409,600
            case B * HW2 * 4:  reg2 = (const float*)d_in[i]; break;  //    102,400
            case B * N * 4:    gt   = (const float*)d_in[i]; break;  //      8,192
            case B * N:        lab  = (const int*)d_in[i];   break;  //      2,048
        }
    }

    dim3 grid(NCHUNKS, B, 2);
    argmin_kernel<<<grid, 256>>>(reg0, reg1, reg2, gt);

    gather_kernel<<<GBLOCKS, 256>>>(cls0, cls1, cls2, reg0, reg1, reg2, gt, lab,
                                    (float*)d_out);
}

// round 8
// speedup vs baseline: 1.9658x; 1.2724x over previous
#include <cuda_runtime.h>
#include <math.h>

#define B       16
#define N       128
#define NC      80
#define HW0     25600
#define HW1     6400
#define HW2     1600
#define CHUNK   800                  // MUST stay <= 1024 (10-bit local idx)
#define NTUP    (3 * B * N)          // 6144 tuples
#define CH0     (HW0 / CHUNK)        // 32
#define CH1     (HW1 / CHUNK)        // 8
#define CH2     (HW2 / CHUNK)        // 2
#define NCHUNKS (CH0 + CH1 + CH2)    // 42
#define GBLOCKS (NTUP / 8)           // 768 gather blocks (8 warps each)

// Scratch (no device allocations allowed)
__device__ unsigned long long g_part[NCHUNKS][B][N];  // per-chunk argmin partials
__device__ float        g_blk[3][GBLOCKS];            // per-block loss partials
__device__ unsigned int g_count;                      // last-block ticket (zero-init; reset each run)

// Packed f32x2 ops (sm_103a; ptxas won't auto-fuse -- must be PTX)
#define PACK_F32X2(out, lo, hi) \
    asm("mov.b64 %0, {%1, %2};" : "=l"(out) : "f"(lo), "f"(hi))
#define UNPACK_U32X2(lo, hi, in) \
    asm("mov.b64 {%0, %1}, %2;" : "=r"(lo), "=r"(hi) : "l"(in))
#define ADD_F32X2(out, a, b) \
    asm("add.rn.f32x2 %0, %1, %2;" : "=l"(out) : "l"(a), "l"(b))
#define MUL_F32X2(out, a, b) \
    asm("mul.rn.f32x2 %0, %1, %2;" : "=l"(out) : "l"(a), "l"(b))
#define FMA_F32X2(out, a, b, c) \
    asm("fma.rn.f32x2 %0, %1, %2, %3;" : "=l"(out) : "l"(a), "l"(b), "l"(c))

// ---------------------------------------------------------------------------
// Kernel 1: per-chunk nearest-pred search, no atomics, no init needed.
// Grid (NCHUNKS, B, 2). Block 256 = 32 lanes x 8 rows; each thread holds 8 gts.
// d2 via packed f32x2 (2 gts / instr). Min-update is INTEGER:
//   key = (d2_bits & 0xFFFFFC00) | p_local   (LOP3)
//   kmin = umin(kmin, key)                   (IMNMX)
// d2>=0 -> float bits monotone as uint; 10-bit mantissa truncation = 2^-13
// relative, far below best/second-best gaps; p_local<800 fits the 10 bits;
// equal truncated d2 -> lowest p_local = first occurrence (argmin semantics).
// Exact d2 is recomputed in gather, so the threshold is unaffected.
// ---------------------------------------------------------------------------
__global__ __launch_bounds__(256)
void argmin_kernel(const float* __restrict__ reg0,
                   const float* __restrict__ reg1,
                   const float* __restrict__ reg2,
                   const float* __restrict__ gt) {
    const int bx = blockIdx.x;   // chunk slot 0..41
    const int b  = blockIdx.y;
    const int gh = blockIdx.z;   // gt half

    int chunk, HW;
    const float* reg;
    if (bx < CH0)            { chunk = bx;               HW = HW0; reg = reg0; }
    else if (bx < CH0 + CH1) { chunk = bx - CH0;         HW = HW1; reg = reg1; }
    else                     { chunk = bx - (CH0 + CH1); HW = HW2; reg = reg2; }

    const int tx = threadIdx.x & 31;
    const int ty = threadIdx.x >> 5;           // 0..7
    const int gbase = gh * 64 + ty * 8;        // first of this thread's 8 gts

    // Pre-negated, packed gt coords: gnx[j] = (-gx[2j], -gx[2j+1])
    unsigned long long gnx[4], gny[4];
    unsigned kmin[8];
    const float* gtb = gt + ((size_t)b * N + gbase) * 4;
#pragma unroll
    for (int j = 0; j < 4; j++) {
        float a0 = -gtb[(2 * j    ) * 4 + 0];
        float a1 = -gtb[(2 * j + 1) * 4 + 0];
        float b0 = -gtb[(2 * j    ) * 4 + 1];
        float b1 = -gtb[(2 * j + 1) * 4 + 1];
        PACK_F32X2(gnx[j], a0, a1);
        PACK_F32X2(gny[j], b0, b1);
    }
#pragma unroll
    for (int i = 0; i < 8; i++) kmin[i] = 0xFFFFFFFFu;

    const float* regb = reg + (size_t)b * HW * 4;
    const int pbase = chunk * CHUNK;
    const int pend  = pbase + CHUNK;

    unsigned plocal = tx;
#pragma unroll 5
    for (int p = pbase + tx; p < pend; p += 32, plocal += 32) {
        float4 v = *reinterpret_cast<const float4*>(regb + (size_t)p * 4);
        unsigned long long pxx, pyy;
        PACK_F32X2(pxx, v.x, v.x);
        PACK_F32X2(pyy, v.y, v.y);
#pragma unroll
        for (int j = 0; j < 4; j++) {
            unsigned long long dx2, dy2, m, d2v;
            ADD_F32X2(dx2, gnx[j], pxx);     // (px-gx, px-gx')
            ADD_F32X2(dy2, gny[j], pyy);
            MUL_F32X2(m, dx2, dx2);
            FMA_F32X2(d2v, dy2, dy2, m);
            unsigned lo, hi;
            UNPACK_U32X2(lo, hi, d2v);
            unsigned k0 = (lo & 0xFFFFFC00u) | plocal;   // LOP3
            unsigned k1 = (hi & 0xFFFFFC00u) | plocal;
            kmin[2 * j]     = umin(kmin[2 * j],     k0); // IMNMX
            kmin[2 * j + 1] = umin(kmin[2 * j + 1], k1);
        }
    }

    // Warp reduce u32 keys; lane 0 writes u64 partial (trunc_d2, global idx).
#pragma unroll
    for (int i = 0; i < 8; i++) {
        unsigned k = kmin[i];
#pragma unroll
        for (int off = 16; off > 0; off >>= 1)
            k = umin(k, __shfl_xor_sync(0xFFFFFFFFu, k, off));
        if (tx == 0) {
            unsigned idx = (unsigned)pbase + (k & 0x3FFu);
            g_part[bx][b][gbase + i] =
                ((unsigned long long)(k & 0xFFFFFC00u) << 32) | idx;
        }
    }
}

// ---------------------------------------------------------------------------
// Kernel 2: fused gather + CE/L1 + full deterministic reduction.
// One warp per (lvl, b, gt) tuple; 8 warps/block, GBLOCKS blocks.
// Recomputes EXACT d2 from reg[id]/gt for the distance threshold.
// Last block (ticket pattern) reduces all block partials and writes outputs.
// ---------------------------------------------------------------------------
__global__ __launch_bounds__(256)
void gather_kernel(const float* __restrict__ cls0,
                   const float* __restrict__ cls1,
                   const float* __restrict__ cls2,
                   const float* __restrict__ reg0,
                   const float* __restrict__ reg1,
                   const float* __restrict__ reg2,
                   const float* __restrict__ gt,
                   const int*   __restrict__ labels,
                   float*       __restrict__ out) {
    const int wib  = threadIdx.x >> 5;                  // warp in block 0..7
    const int w    = blockIdx.x * 8 + wib;              // tuple id
    const int lane = threadIdx.x & 31;

    const int lvl = w / (B * N);
    const int rem = w - lvl * (B * N);
    const int b   = rem / N;
    const int g   = rem - b * N;

    const float* cls; const float* reg; int HW, s0, nch;
    if (lvl == 0)      { cls = cls0; reg = reg0; HW = HW0; s0 = 0;         nch = CH0; }
    else if (lvl == 1) { cls = cls1; reg = reg1; HW = HW1; s0 = CH0;       nch = CH1; }
    else               { cls = cls2; reg = reg2; HW = HW2; s0 = CH0 + CH1; nch = CH2; }

    // Min over this level's chunk partials (lane c holds chunk c's key).
    unsigned long long key = 0xFFFFFFFFFFFFFFFFULL;
    if (lane < nch) key = g_part[s0 + lane][b][g];
#pragma unroll
    for (int off = 16; off > 0; off >>= 1) {
        unsigned long long k2 = __shfl_xor_sync(0xFFFFFFFFu, key, off);
        key = (k2 < key) ? k2 : key;
    }
    // key now uniform across warp
    unsigned id = (unsigned)key;

    const float* gtr = gt + ((size_t)b * N + g) * 4;

    // CE via warp logsumexp over 80 classes
    const float* crow = cls + ((size_t)b * HW + id) * NC;
    float x0 = -__int_as_float(0x7F800000), x1 = x0, x2 = x0;
    if (lane < NC)      x0 = crow[lane];
    if (lane + 32 < NC) x1 = crow[lane + 32];
    if (lane + 64 < NC) x2 = crow[lane + 64];
    float mx = fmaxf(x0, fmaxf(x1, x2));
#pragma unroll
    for (int off = 16; off > 0; off >>= 1)
        mx = fmaxf(mx, __shfl_xor_sync(0xFFFFFFFFu, mx, off));
    float sm = 0.0f;
    if (lane < NC)      sm += expf(x0 - mx);
    if (lane + 32 < NC) sm += expf(x1 - mx);
    if (lane + 64 < NC) sm += expf(x2 - mx);
#pragma unroll
    for (int off = 16; off > 0; off >>= 1)
        sm += __shfl_xor_sync(0xFFFFFFFFu, sm, off);
    float lse = mx + logf(sm);

    __shared__ float s_ce[8], s_l1[8], s_w[8];
    __shared__ int   s_last;

    if (lane == 0) {
        const float* rrow = reg + ((size_t)b * HW + id) * 4;
        // Exact d2 recompute (same expression/rounding as reference scale)
        float dx = gtr[0] - rrow[0];
        float dy = gtr[1] - rrow[1];
        float d2 = dx * dx + dy * dy;
        float wgt = (sqrtf(d2) < 2.5f) ? 1.0f : 0.0f;

        int lab = labels[b * N + g];
        float ce = lse - crow[lab];
        float l1 = fabsf(rrow[0] - gtr[0]) + fabsf(rrow[1] - gtr[1]) +
                   fabsf(rrow[2] - gtr[2]) + fabsf(rrow[3] - gtr[3]);
        s_ce[wib] = ce * wgt;
        s_l1[wib] = l1 * wgt;
        s_w[wib]  = wgt;
    }
    __syncthreads();

    // Block partials + ticket
    if (threadIdx.x == 0) {
        float a = 0.0f, c = 0.0f, nn = 0.0f;
#pragma unroll
        for (int i = 0; i < 8; i++) { a += s_ce[i]; c += s_l1[i]; nn += s_w[i]; }
        g_blk[0][blockIdx.x] = a;
        g_blk[1][blockIdx.x] = c;
        g_blk[2][blockIdx.x] = nn;
        __threadfence();
        unsigned t = atomicAdd(&g_count, 1u);
        s_last = (t == GBLOCKS - 1);
    }
    __syncthreads();

    if (!s_last) return;

    // Last block: deterministic tree reduction of GBLOCKS partials.
    __shared__ float r0[256], r1[256], r2[256];
    int tid = threadIdx.x;
    float a = 0.0f, c = 0.0f, nn = 0.0f;
    for (int i = tid; i < GBLOCKS; i += 256) {
        a  += g_blk[0][i];
        c  += g_blk[1][i];
        nn += g_blk[2][i];
    }
    r0[tid] = a; r1[tid] = c; r2[tid] = nn;
    __syncthreads();
    for (int off = 128; off > 0; off >>= 1) {
        if (tid < off) {
            r0[tid] += r0[tid + off];
            r1[tid] += r1[tid + off];
            r2[tid] += r2[tid + off];
        }
        __syncthreads();
    }
    if (tid == 0) {
        float np    = r2[0];
        float denom = fmaxf(np, 1.0f);
        out[0] = r0[0] / denom;
        out[1] = r1[0] / denom;
        out[2] = np;
        g_count = 0;   // reset ticket for next graph replay
    }
}

// ---------------------------------------------------------------------------
// Bind inputs BY ELEMENT COUNT (metadata order is interleaved:
// cls_0, reg_0, cls_1, reg_1, cls_2, reg_2, gt, labels). All 8 element
// counts are distinct, so size-based binding is unambiguous.
// ---------------------------------------------------------------------------
extern "C" void kernel_launch(void* const* d_in, const int* in_sizes, int n_in,
                              void* d_out, int out_size) {
    const float* cls0 = 0; const float* cls1 = 0; const float* cls2 = 0;
    const float* reg0 = 0; const float* reg1 = 0; const float* reg2 = 0;
    const float* gt   = 0; const int*   lab  = 0;

    for (int i = 0; i < n_in; i++) {
        switch (in_sizes[i]) {
            case B * HW0 * NC: cls0 = (const float*)d_in[i]; break;  // 32,768,000
            case B * HW1 * NC: cls1 = (const float*)d_in[i]; break;  //  8,192,000
            case B * HW2 * NC: cls2 = (const float*)d_in[i]; break;  //  2,048,000
            case B * HW0 * 4:  reg0 = (const float*)d_in[i]; break;  //  1,638,400
            case B * HW1 * 4:  reg1 = (const float*)d_in[i]; break;  //    409,600
            case B * HW2 * 4:  reg2 = (const float*)d_in[i]; break;  //    102,400
            case B * N * 4:    gt   = (const float*)d_in[i]; break;  //      8,192
            case B * N:        lab  = (const int*)d_in[i];   break;  //      2,048
        }
    }

    dim3 grid(NCHUNKS, B, 2);
    argmin_kernel<<<grid, 256>>>(reg0, reg1, reg2, gt);

    gather_kernel<<<GBLOCKS, 256>>>(cls0, cls1, cls2, reg0, reg1, reg2, gt, lab,
                                    (float*)d_out);
}